// round 2
// baseline (speedup 1.0000x reference)
#include <cuda_runtime.h>
#include <cuda_bf16.h>

// Problem: B=4, C=32, H=64, W=128, D=192/4=48
// Output (B, 2C, D, H, W) fp32:
//   out[b,c2,d,h,w] = (w >= d) ? ((c2 < C) ? left[b,c2,h,w]
//                                          : right[b,c2-C,h,w-d])
//                              : 0
//
// HBM-write-bound: output ~403 MB, inputs 8 MB (L2-resident, reused 48x).
// One thread per output float4; grid (8, D, B*2C) so all index math is
// shifts/ands (no integer divide). Stores fully coalesced (512 B/warp).

#define B_ 4
#define C_ 32
#define H_ 64
#define W_ 128
#define D_ 48

__global__ void __launch_bounds__(256)
cost_volume_concat_kernel(const float* __restrict__ left,
                          const float* __restrict__ right,
                          float* __restrict__ out)
{
    // blockIdx.z : b*2C + c2   (0..255)
    // blockIdx.y : d           (0..47)
    // blockIdx.x * 256 + tid : linear (h, w4) within the slice, 64*32 = 2048
    const int c2 = blockIdx.z & 63;
    const int b  = blockIdx.z >> 6;
    const int d  = blockIdx.y;

    const int hw = blockIdx.x * blockDim.x + threadIdx.x;  // 0..2047
    const int w4 = hw & 31;
    const int h  = hw >> 5;

    const int  c       = c2 & (C_ - 1);
    const bool isRight = (c2 >= C_);

    // (b, c, h, :) row base in the 4D source (row length W_=128).
    const float* src = (isRight ? right : left)
                       + (((b * C_ + c) * H_ + h) << 7);

    const int w0 = w4 << 2;
    float4 v;

    if (!isRight) {
        // Aligned vector load; mask lanes w < d.
        v = __ldg(reinterpret_cast<const float4*>(src) + w4);
        if (w0 + 0 < d) v.x = 0.0f;
        if (w0 + 1 < d) v.y = 0.0f;
        if (w0 + 2 < d) v.z = 0.0f;
        if (w0 + 3 < d) v.w = 0.0f;
    } else {
        // Shifted row: unaligned, use scalar L2-hit loads.
        int w;
        w = w0 + 0; v.x = (w >= d) ? __ldg(src + w - d) : 0.0f;
        w = w0 + 1; v.y = (w >= d) ? __ldg(src + w - d) : 0.0f;
        w = w0 + 2; v.z = (w >= d) ? __ldg(src + w - d) : 0.0f;
        w = w0 + 3; v.w = (w >= d) ? __ldg(src + w - d) : 0.0f;
    }

    // Output float4 index: (((b*64 + c2)*48 + d)*64 + h)*32 + w4
    const long long oidx =
        ((long long)((blockIdx.z * D_ + d)) << 11) + hw;
    reinterpret_cast<float4*>(out)[oidx] = v;
}

extern "C" void kernel_launch(void* const* d_in, const int* in_sizes, int n_in,
                              void* d_out, int out_size)
{
    const float* left  = (const float*)d_in[0];
    const float* right = (const float*)d_in[1];
    float* out = (float*)d_out;

    dim3 grid(8, D_, B_ * 2 * C_);   // 8*256 = 2048 = H*W/4 per slice
    cost_volume_concat_kernel<<<grid, 256>>>(left, right, out);
}

// round 3
// speedup vs baseline: 1.4657x; 1.4657x over previous
#include <cuda_runtime.h>
#include <cuda_bf16.h>

// Problem: B=4, C=32, H=64, W=128, D=192/4=48
// out[b,c2,d,h,w] = (w >= d) ? ((c2 < C) ? left[b,c2,h,w]
//                                        : right[b,c2-C,h,w-d]) : 0
//
// One block per source row-pair (b,c,h): 8192 blocks x 256 threads.
// Rows staged in smem once; each thread owns a fixed (half, w4, d-group)
// and loops over 12 d-values with pure pointer-increment addressing.
// Stores: 1 float4 per thread per iter, warp = one contiguous 512B row.

#define B_ 4
#define C_ 32
#define H_ 64
#define W_ 128
#define D_ 48

__global__ void __launch_bounds__(256)
cost_volume_concat_kernel(const float* __restrict__ left,
                          const float* __restrict__ right,
                          float* __restrict__ out)
{
    __shared__ float sL[W_];
    __shared__ float sR[W_];

    // blockIdx.x = (b*C + c)*H + h,  0..8191
    const int blk = blockIdx.x;
    const int h   = blk & (H_ - 1);
    const int bc  = blk >> 6;            // b*C + c, 0..127
    const int b   = bc >> 5;
    const int c   = bc & (C_ - 1);

    const int tid = threadIdx.x;

    // Stage both 512B rows (32 float4 each) into smem.
    const float* lrow = left  + ((long long)blk << 7);
    const float* rrow = right + ((long long)blk << 7);
    if (tid < 32) {
        reinterpret_cast<float4*>(sL)[tid] =
            __ldg(reinterpret_cast<const float4*>(lrow) + tid);
    } else if (tid < 64) {
        reinterpret_cast<float4*>(sR)[tid - 32] =
            __ldg(reinterpret_cast<const float4*>(rrow) + (tid - 32));
    }
    __syncthreads();

    // Thread mapping: w4 = tid&31, half = (tid>>5)&1, dg = tid>>6 (0..3).
    // Thread covers d = dg, dg+4, ..., dg+44  (12 iterations).
    const int w4   = tid & 31;
    const int half = (tid >> 5) & 1;
    const int dg   = tid >> 6;
    const int w0   = w4 << 2;

    // Output float4 index: ((b*64 + half*32 + c)*48 + d)*2048 + h*32 + w4
    const int c2 = half * C_ + c;
    float4* o = reinterpret_cast<float4*>(out)
              + ((long long)((b * 2 * C_ + c2) * D_ + dg) << 11)
              + (h << 5) + w4;
    const long long dstride = 4LL << 11;   // 4 d-steps

    if (half == 0) {
        // Left: value is d-invariant; only the mask changes.
        const float4 v = reinterpret_cast<const float4*>(sL)[w4];
        #pragma unroll
        for (int i = 0; i < 12; i++) {
            const int d = dg + 4 * i;
            float4 u = v;
            if (w0 + 0 < d) u.x = 0.0f;
            if (w0 + 1 < d) u.y = 0.0f;
            if (w0 + 2 < d) u.z = 0.0f;
            if (w0 + 3 < d) u.w = 0.0f;
            __stcs(o, u);
            o += dstride;
        }
    } else {
        // Right: shifted read from smem (conflict-free: consecutive lanes,
        // consecutive addresses).
        #pragma unroll
        for (int i = 0; i < 12; i++) {
            const int d = dg + 4 * i;
            float4 u;
            u.x = (w0 + 0 >= d) ? sR[w0 + 0 - d] : 0.0f;
            u.y = (w0 + 1 >= d) ? sR[w0 + 1 - d] : 0.0f;
            u.z = (w0 + 2 >= d) ? sR[w0 + 2 - d] : 0.0f;
            u.w = (w0 + 3 >= d) ? sR[w0 + 3 - d] : 0.0f;
            __stcs(o, u);
            o += dstride;
        }
    }
}

extern "C" void kernel_launch(void* const* d_in, const int* in_sizes, int n_in,
                              void* d_out, int out_size)
{
    const float* left  = (const float*)d_in[0];
    const float* right = (const float*)d_in[1];
    float* out = (float*)d_out;

    cost_volume_concat_kernel<<<B_ * C_ * H_, 256>>>(left, right, out);
}

// round 6
// speedup vs baseline: 1.4695x; 1.0026x over previous
#include <cuda_runtime.h>
#include <cuda_bf16.h>

// Problem: B=4, C=32, H=64, W=128, D=192/4=48
// out[b,c2,d,h,w] = (w >= d) ? ((c2 < C) ? left[b,c2,h,w]
//                                        : right[b,c2-C,h,w-d]) : 0
//
// One block per source row-pair (b,c,h): 8192 blocks x 256 threads.
// Left row staged in smem once. Right row staged as FOUR pre-shifted,
// zero-padded copies (sRs[s][x] = right[x-48-s]), so each warp (which has a
// fixed d mod 4) reads one aligned LDS.128 per output float4 — no per-element
// predication, masking is implicit in the zero padding.

#define B_ 4
#define C_ 32
#define H_ 64
#define W_ 128
#define D_ 48
#define PAD_ 48
#define SRW_ 256   // padded row length per shifted copy (pow2 for cheap idx math)

__global__ void __launch_bounds__(256)
cost_volume_concat_kernel(const float* __restrict__ left,
                          const float* __restrict__ right,
                          float* __restrict__ out)
{
    __shared__ float sL[W_];
    __shared__ float sRs[4][SRW_];   // sRs[s][x] = right_row[x - PAD_ - s], else 0

    // blockIdx.x = (b*C + c)*H + h,  0..8191
    const int blk = blockIdx.x;
    const int tid = threadIdx.x;

    const float* lrow = left  + ((long long)blk << 7);
    const float* rrow = right + ((long long)blk << 7);

    // Stage left row (32 float4).
    if (tid < 32) {
        reinterpret_cast<float4*>(sL)[tid] =
            __ldg(reinterpret_cast<const float4*>(lrow) + tid);
    }

    // Build 4 shifted zero-padded right-row copies (4*256 floats, 4/thread).
    #pragma unroll
    for (int k = 0; k < 4; k++) {
        const int idx = tid + (k << 8);      // 0..1023
        const int s   = idx >> 8;            // copy id 0..3
        const int x   = idx & 255;
        const int e   = x - PAD_ - s;        // source element
        sRs[s][x] = (e >= 0 && e < W_) ? __ldg(rrow + e) : 0.0f;
    }
    __syncthreads();

    // Thread mapping: w4 = tid&31, half = (tid>>5)&1, dg = tid>>6 (0..3).
    // Thread covers d = dg, dg+4, ..., dg+44 (12 iterations).
    const int w4   = tid & 31;
    const int half = (tid >> 5) & 1;
    const int dg   = tid >> 6;
    const int w0   = w4 << 2;

    const int h  = blk & (H_ - 1);
    const int bc = blk >> 6;                 // b*C + c
    const int b  = bc >> 5;
    const int c  = bc & (C_ - 1);
    const int c2 = half * C_ + c;

    // Output float4 index: ((b*64 + c2)*48 + d)*2048 + h*32 + w4
    float4* o = reinterpret_cast<float4*>(out)
              + ((long long)((b * 2 * C_ + c2) * D_ + dg) << 11)
              + (h << 5) + w4;
    const long long dstride = 4LL << 11;     // 4 d-steps

    if (half == 0) {
        // Left: value is d-invariant; only the mask changes.
        const float4 v = reinterpret_cast<const float4*>(sL)[w4];
        #pragma unroll
        for (int i = 0; i < 12; i++) {
            const int d = dg + 4 * i;
            float4 u = v;
            if (w0 + 0 < d) u.x = 0.0f;
            if (w0 + 1 < d) u.y = 0.0f;
            if (w0 + 2 < d) u.z = 0.0f;
            if (w0 + 3 < d) u.w = 0.0f;
            __stcs(o, u);
            o += dstride;
        }
    } else {
        // Right: one aligned LDS.128 per iter from the dg-shifted copy.
        // sRs[dg][PAD_ + w0 + k - 4i] = right[w0+k - (dg+4i)] (zero if w<d).
        const float* base = &sRs[dg][PAD_ + w0];
        #pragma unroll
        for (int i = 0; i < 12; i++) {
            const float4 u = *reinterpret_cast<const float4*>(base - 4 * i);
            __stcs(o, u);
            o += dstride;
        }
    }
}

extern "C" void kernel_launch(void* const* d_in, const int* in_sizes, int n_in,
                              void* d_out, int out_size)
{
    const float* left  = (const float*)d_in[0];
    const float* right = (const float*)d_in[1];
    float* out = (float*)d_out;

    cost_volume_concat_kernel<<<B_ * C_ * H_, 256>>>(left, right, out);
}